// round 2
// baseline (speedup 1.0000x reference)
#include <cuda_runtime.h>
#include <cstdint>
#include <float.h>
#include <math.h>

#define Nn    4096
#define NMASK 4095
#define Hh    64
#define KNN   15
#define MAXE  65536
#define NK    (Nn*KNN)

// ---------------- scratch (device globals; no allocs allowed) ----------------
__device__ int      g_is64;
__device__ float    g_y[Nn*Hh];
__device__ unsigned g_ykey[Nn*Hh];
__device__ unsigned g_minkey[Nn*Hh];
__device__ float    g_feats[Nn*Hh];
__device__ float    g_q[Nn*Hh];
__device__ float    g_k[Nn*Hh];
__device__ int      g_knn[NK];
__device__ float    g_attn[MAXE];
__device__ unsigned g_rowmaxkey[Nn];
__device__ float    g_rowsum[Nn];
__device__ int      g_rowcnt[Nn];
__device__ int      g_colcnt[Nn];
__device__ int      g_rowptr[Nn+1];
__device__ int      g_colptr[Nn+1];
__device__ int      g_rowfill[Nn];
__device__ int      g_colfill[Nn];
__device__ int      g_cols[MAXE];
__device__ float    g_svals[MAXE];
__device__ int      g_cscrows[MAXE];
__device__ float    g_cscsvals[MAXE];

// ---------------- helpers ----------------
// order-preserving float<->uint: encode monotonic increasing
__device__ __forceinline__ unsigned fenc(float f) {
    unsigned u = __float_as_uint(f);
    return (u & 0x80000000u) ? ~u : (u ^ 0x80000000u);
}
__device__ __forceinline__ float fdec(unsigned e) {
    unsigned u = (e & 0x80000000u) ? (e ^ 0x80000000u) : ~e;
    return __uint_as_float(u);
}
__device__ __forceinline__ void edge_rc(const long long* e64, const int* e32,
                                        int E, int is64, int e, int& r, int& c) {
    if (is64) { r = ((int)e64[e]) & NMASK; c = ((int)e64[E + e]) & NMASK; }
    else      { r = e32[e] & NMASK;        c = e32[E + e] & NMASK; }
}
__device__ __forceinline__ unsigned long long umin64(unsigned long long a,
                                                     unsigned long long b) {
    return a < b ? a : b;
}

// ---------------- kernels ----------------
// detect whether edge_index buffer is int64 or int32
__global__ void k_detect(const unsigned long long* ei) {
    if (threadIdx.x == 0 && blockIdx.x == 0) {
        int ok64 = 1;
        for (int i = 0; i < 64; ++i) {
            unsigned long long v = ei[i];
            if ((v >> 32) != 0ULL || (v & 0xFFFFFFFFULL) >= (unsigned)Nn) { ok64 = 0; break; }
        }
        g_is64 = ok64;
    }
}

__global__ void k_init() {
    int t = blockIdx.x * blockDim.x + threadIdx.x;
    if (t < Nn * Hh) g_minkey[t] = 0xFFFFFFFFu;
    if (t < Nn) {
        g_rowmaxkey[t] = 0u;
        g_rowsum[t] = 0.0f;
        g_rowcnt[t] = 0;
        g_colcnt[t] = 0;
    }
}

// y = x @ W_theta^T (bias folded in later); also encoded keys for min-scatter
__global__ void k_y(const float* __restrict__ x, const float* __restrict__ Wt) {
    int t = blockIdx.x * blockDim.x + threadIdx.x;
    if (t >= Nn * Hh) return;
    int i = t >> 6, f = t & 63;
    float x0 = x[i*3+0], x1 = x[i*3+1], x2 = x[i*3+2];
    float v = Wt[f*3+0]*x0 + Wt[f*3+1]*x1 + Wt[f*3+2]*x2;
    g_y[t] = v;
    g_ykey[t] = fenc(v);
}

// brute-force kNN, JAX top_k semantics (ascending d2, ties -> smaller index)
__global__ void k_knn(const float* __restrict__ x) {
    __shared__ unsigned long long keys[Nn];    // 32 KB
    __shared__ unsigned long long smin[256];   // 2 KB
    int i = blockIdx.x;
    int t = threadIdx.x;  // 256 threads

    float xi0 = x[i*3+0], xi1 = x[i*3+1], xi2 = x[i*3+2];
    float sqi = xi0*xi0 + xi1*xi1 + xi2*xi2;

    for (int j = t; j < Nn; j += 256) {
        unsigned long long key = 0xFFFFFFFFFFFFFFFFULL;
        if (j != i) {
            float y0 = x[j*3+0], y1 = x[j*3+1], y2 = x[j*3+2];
            float dot = xi0*y0 + xi1*y1 + xi2*y2;
            float sqj = y0*y0 + y1*y1 + y2*y2;
            float d2 = (sqi - 2.0f*dot) + sqj;     // matches (sq_i - 2*xy) + sq_j
            key = ((unsigned long long)fenc(d2) << 32) | (unsigned)j;
        }
        keys[j] = key;
    }
    __syncthreads();

    for (int p = 0; p < KNN; ++p) {
        unsigned long long m = 0xFFFFFFFFFFFFFFFFULL;
        #pragma unroll
        for (int j = t; j < Nn; j += 256) m = umin64(m, keys[j]);
        smin[t] = m;
        __syncthreads();
        #pragma unroll
        for (int s = 128; s > 0; s >>= 1) {
            if (t < s) smin[t] = umin64(smin[t], smin[t + s]);
            __syncthreads();
        }
        if (t == 0) {
            unsigned long long mm = smin[0];
            int j = (int)(mm & 0xFFFFFFFFu);
            g_knn[i*KNN + p] = j;
            keys[j] = 0xFFFFFFFFFFFFFFFFULL;       // mask out for next pass
        }
        __syncthreads();
    }
}

// per-(node,feature) min of y over neighbors, across extended edges (input + kNN)
__global__ void k_minscatter(const long long* __restrict__ e64,
                             const int* __restrict__ e32, int E) {
    int is64 = g_is64;
    long long tot = (long long)(E + NK) * Hh;
    long long t = (long long)blockIdx.x * blockDim.x + threadIdx.x;
    if (t >= tot) return;
    int f = (int)(t & 63);
    long long e = t >> 6;
    int row, col;
    if (e < E) { edge_rc(e64, e32, E, is64, (int)e, row, col); }
    else       { int ke = (int)(e - E); row = ke / KNN; col = g_knn[ke] & NMASK; }
    atomicMin(&g_minkey[row*Hh + f], g_ykey[col*Hh + f]);
}

// feats = (y + b_theta - min) @ W_phi^T + b_phi      (32 rows per block)
__global__ void k_feats(const float* __restrict__ bth,
                        const float* __restrict__ Wphi,
                        const float* __restrict__ bphi) {
    __shared__ float sWt[Hh*Hh];   // transposed: sWt[h*64+f]
    __shared__ float sA[32*Hh];
    int t = threadIdx.x;
    int r0 = blockIdx.x * 32;
    for (int idx = t; idx < Hh*Hh; idx += 256) {
        int f = idx >> 6, h = idx & 63;
        sWt[h*Hh + f] = Wphi[idx];
    }
    for (int idx = t; idx < 32*Hh; idx += 256) {
        int f = idx & 63;
        int gi = r0*Hh + idx;
        sA[idx] = g_y[gi] + bth[f] - fdec(g_minkey[gi]);
    }
    __syncthreads();
    for (int o = t; o < 32*Hh; o += 256) {
        int li = o >> 6, f = o & 63;
        float acc = bphi[f];
        #pragma unroll
        for (int h = 0; h < Hh; ++h) acc += sA[li*Hh + h] * sWt[h*Hh + f];
        g_feats[r0*Hh + o] = acc;
    }
}

// q = feats @ W_q^T,  k = feats @ W_k^T
__global__ void k_qk(const float* __restrict__ Wq, const float* __restrict__ Wk) {
    __shared__ float sWq[Hh*Hh];
    __shared__ float sWk[Hh*Hh];
    __shared__ float sF[32*Hh];
    int t = threadIdx.x;
    int r0 = blockIdx.x * 32;
    for (int idx = t; idx < Hh*Hh; idx += 256) {
        int f = idx >> 6, h = idx & 63;
        sWq[h*Hh + f] = Wq[idx];
        sWk[h*Hh + f] = Wk[idx];
    }
    for (int idx = t; idx < 32*Hh; idx += 256) sF[idx] = g_feats[r0*Hh + idx];
    __syncthreads();
    for (int o = t; o < 32*Hh; o += 256) {
        int li = o >> 6, f = o & 63;
        float aq = 0.0f, ak = 0.0f;
        #pragma unroll
        for (int h = 0; h < Hh; ++h) {
            float fv = sF[li*Hh + h];
            aq += fv * sWq[h*Hh + f];
            ak += fv * sWk[h*Hh + f];
        }
        g_q[r0*Hh + o] = aq;
        g_k[r0*Hh + o] = ak;
    }
}

// attn[e] = dot(q[row], k[col]); row-max (encoded-uint atomicMax) and CSR/CSC counts
__global__ void k_attn(const long long* __restrict__ e64,
                       const int* __restrict__ e32, int E) {
    int is64 = g_is64;
    int w = (blockIdx.x * blockDim.x + threadIdx.x) >> 5;
    int lane = threadIdx.x & 31;
    if (w >= E) return;
    int row, col;
    edge_rc(e64, e32, E, is64, w, row, col);
    float a = g_q[row*Hh + lane]      * g_k[col*Hh + lane]
            + g_q[row*Hh + 32 + lane] * g_k[col*Hh + 32 + lane];
    #pragma unroll
    for (int o = 16; o; o >>= 1) a += __shfl_xor_sync(0xffffffffu, a, o);
    if (lane == 0) {
        g_attn[w] = a;
        atomicMax(&g_rowmaxkey[row], fenc(a));
        atomicAdd(&g_rowcnt[row], 1);
        atomicAdd(&g_colcnt[col], 1);
    }
}

__global__ void k_exp(const long long* __restrict__ e64,
                      const int* __restrict__ e32, int E) {
    int is64 = g_is64;
    int e = blockIdx.x * blockDim.x + threadIdx.x;
    if (e >= E) return;
    int row, col;
    edge_rc(e64, e32, E, is64, e, row, col);
    float v = expf(g_attn[e] - fdec(g_rowmaxkey[row]));
    g_attn[e] = v;
    atomicAdd(&g_rowsum[row], v);
}

// exclusive scan of counts -> ptrs (+fill copies). block 0: rows, block 1: cols.
__global__ void k_scan() {
    const int* cnt = blockIdx.x ? g_colcnt : g_rowcnt;
    int* ptr  = blockIdx.x ? g_colptr  : g_rowptr;
    int* fill = blockIdx.x ? g_colfill : g_rowfill;
    __shared__ int sh[1024];
    int t = threadIdx.x;
    int v[4]; int s = 0;
    #pragma unroll
    for (int k = 0; k < 4; ++k) { v[k] = cnt[t*4 + k]; s += v[k]; }
    sh[t] = s;
    __syncthreads();
    for (int d = 1; d < 1024; d <<= 1) {
        int add = (t >= d) ? sh[t - d] : 0;
        __syncthreads();
        sh[t] += add;
        __syncthreads();
    }
    int excl = sh[t] - s;
    #pragma unroll
    for (int k = 0; k < 4; ++k) { ptr[t*4+k] = excl; fill[t*4+k] = excl; excl += v[k]; }
    if (t == 1023) ptr[Nn] = excl;
}

// normalize softmax + scatter into CSR (by row) and CSC (by col); duplicates kept
__global__ void k_scatter(const long long* __restrict__ e64,
                          const int* __restrict__ e32, int E) {
    int is64 = g_is64;
    int e = blockIdx.x * blockDim.x + threadIdx.x;
    if (e >= E) return;
    int row, col;
    edge_rc(e64, e32, E, is64, e, row, col);
    float sc = g_attn[e] / g_rowsum[row];
    int p = atomicAdd(&g_rowfill[row], 1);
    g_cols[p] = col; g_svals[p] = sc;
    int c = atomicAdd(&g_colfill[col], 1);
    g_cscrows[c] = row; g_cscsvals[c] = sc;
}

// A_s[i,:] = sum_{p in S-row i} s * sum_{q in A-row cols[p]} (S^T col cols[q])
__global__ void k_out(float* __restrict__ out) {
    __shared__ float orow[Nn];   // 16 KB
    int i = blockIdx.x;
    int t = threadIdx.x;         // 256
    for (int j = t; j < Nn; j += 256) orow[j] = 0.0f;
    __syncthreads();
    int r0 = g_rowptr[i], r1 = g_rowptr[i+1];
    for (int p = r0; p < r1; ++p) {
        int k = g_cols[p];
        float s = g_svals[p];
        int a0 = g_rowptr[k], a1 = g_rowptr[k+1];
        for (int qq = a0 + t; qq < a1; qq += 256) {
            int l = g_cols[qq];              // each A duplicate contributes 1
            int c0 = g_colptr[l], c1 = g_colptr[l+1];
            for (int r = c0; r < c1; ++r)
                atomicAdd(&orow[g_cscrows[r]], s * g_cscsvals[r]);
        }
    }
    __syncthreads();
    float4* o4 = (float4*)(out + (size_t)i * Nn);
    for (int j = t; j < Nn/4; j += 256)
        o4[j] = make_float4(orow[4*j], orow[4*j+1], orow[4*j+2], orow[4*j+3]);
}

// ---------------- launch ----------------
extern "C" void kernel_launch(void* const* d_in, const int* in_sizes, int n_in,
                              void* d_out, int out_size) {
    const float* x    = (const float*)d_in[0];
    const void*  ei   = d_in[1];
    const float* Wth  = (const float*)d_in[2];
    const float* bth  = (const float*)d_in[3];
    const float* Wphi = (const float*)d_in[4];
    const float* bphi = (const float*)d_in[5];
    const float* Wq   = (const float*)d_in[6];
    const float* Wk   = (const float*)d_in[7];
    float* out = (float*)d_out;

    int E = in_sizes[1] / 2;
    const long long* e64 = (const long long*)ei;
    const int*       e32 = (const int*)ei;

    k_detect<<<1, 32>>>((const unsigned long long*)ei);
    k_init<<<(Nn*Hh + 255)/256, 256>>>();
    k_y<<<(Nn*Hh + 255)/256, 256>>>(x, Wth);
    k_knn<<<Nn, 256>>>(x);
    long long tot = (long long)(E + NK) * Hh;
    k_minscatter<<<(int)((tot + 255)/256), 256>>>(e64, e32, E);
    k_feats<<<Nn/32, 256>>>(bth, Wphi, bphi);
    k_qk<<<Nn/32, 256>>>(Wq, Wk);
    k_attn<<<(E*32 + 255)/256, 256>>>(e64, e32, E);
    k_exp<<<(E + 255)/256, 256>>>(e64, e32, E);
    k_scan<<<2, 1024>>>();
    k_scatter<<<(E + 255)/256, 256>>>(e64, e32, E);
    k_out<<<Nn, 256>>>(out);
}

// round 3
// speedup vs baseline: 1.9264x; 1.9264x over previous
#include <cuda_runtime.h>
#include <cstdint>
#include <float.h>

#define Nn    4096
#define NMASK 4095
#define Hh    64
#define KNN   15
#define MAXE  65536
#define NK    (Nn*KNN)
#define XMAX  (MAXE+NK)
#define U64MAX 0xFFFFFFFFFFFFFFFFULL

// ---------------- scratch (device globals; no allocs) ----------------
__device__ int      g_is64;
__device__ float    g_y[Nn*Hh];
__device__ float    g_minv[Nn*Hh];
__device__ float    g_feats[Nn*Hh];
__device__ float    g_q[Nn*Hh];
__device__ float    g_k[Nn*Hh];
__device__ int      g_knn[NK];
__device__ float    g_attn[MAXE];
__device__ unsigned g_rowmaxkey[Nn];
__device__ float    g_rowsum[Nn];
__device__ int      g_rowcnt[Nn];
__device__ int      g_colcnt[Nn];
__device__ int      g_rowptr[Nn+1];
__device__ int      g_colptr[Nn+1];
__device__ int      g_rowfill[Nn];
__device__ int      g_colfill[Nn];
__device__ int      g_xfill[Nn];
__device__ int      g_xcols[XMAX];
__device__ unsigned long long g_rowpack[MAXE];  // (f32bits(val)<<32)|col  CSR of S
__device__ unsigned long long g_cscpack[MAXE];  // (f32bits(val)<<32)|row  CSC of S

// ---------------- helpers ----------------
__device__ __forceinline__ unsigned fenc(float f) {
    unsigned u = __float_as_uint(f);
    return (u & 0x80000000u) ? ~u : (u ^ 0x80000000u);
}
__device__ __forceinline__ float fdec(unsigned e) {
    unsigned u = (e & 0x80000000u) ? (e ^ 0x80000000u) : ~e;
    return __uint_as_float(u);
}
__device__ __forceinline__ void edge_rc(const long long* e64, const int* e32,
                                        int E, int is64, int e, int& r, int& c) {
    if (is64) { r = ((int)e64[e]) & NMASK; c = ((int)e64[E + e]) & NMASK; }
    else      { r = e32[e] & NMASK;        c = e32[E + e] & NMASK; }
}
__device__ __forceinline__ unsigned long long umin64(unsigned long long a,
                                                     unsigned long long b) {
    return a < b ? a : b;
}

// ---------------- kernels ----------------
__global__ void k_detect(const unsigned long long* ei) {
    if (threadIdx.x == 0 && blockIdx.x == 0) {
        int ok64 = 1;
        for (int i = 0; i < 64; ++i) {
            unsigned long long v = ei[i];
            if ((v >> 32) != 0ULL || (v & 0xFFFFFFFFULL) >= (unsigned)Nn) { ok64 = 0; break; }
        }
        g_is64 = ok64;
    }
}

__global__ void k_init() {
    int t = blockIdx.x * blockDim.x + threadIdx.x;
    if (t < Nn) {
        g_rowmaxkey[t] = 0u;
        g_rowsum[t] = 0.0f;
        g_rowcnt[t] = 0;
        g_colcnt[t] = 0;
    }
}

// y = x @ W_theta^T (bias folded later)
__global__ void k_y(const float* __restrict__ x, const float* __restrict__ Wt) {
    int t = blockIdx.x * blockDim.x + threadIdx.x;
    if (t >= Nn * Hh) return;
    int i = t >> 6, f = t & 63;
    float x0 = x[i*3+0], x1 = x[i*3+1], x2 = x[i*3+2];
    g_y[t] = Wt[f*3+0]*x0 + Wt[f*3+1]*x1 + Wt[f*3+2]*x2;
}

// kNN: warp per query. Points in smem (48KB), per-lane sorted top-15 in regs,
// then 32-way merge in smem (points buffer reused after block sync).
__global__ void k_knn(const float* __restrict__ x) {
    __shared__ __align__(16) unsigned char sbuf[49152];
    float2* pxy = (float2*)sbuf;                 // [4096] 32KB
    float*  pz  = (float*)(sbuf + 32768);        // [4096] 16KB
    int t = threadIdx.x, lane = t & 31, w = t >> 5;

    for (int idx = t; idx < Nn*3; idx += 256) {
        float v = x[idx];
        int j = idx / 3, c = idx - j*3;
        if (c == 0)      pxy[j].x = v;
        else if (c == 1) pxy[j].y = v;
        else             pz[j]    = v;
    }
    __syncthreads();

    int i = blockIdx.x * 8 + w;
    float2 xi = pxy[i]; float xz = pz[i];
    float sqi = xi.x*xi.x + xi.y*xi.y + xz*xz;

    unsigned long long kk[KNN];
    #pragma unroll
    for (int q = 0; q < KNN; ++q) kk[q] = U64MAX;

    for (int c = 0; c < 128; ++c) {
        int j = lane + 32*c;
        float2 p = pxy[j]; float z = pz[j];
        float dot = xi.x*p.x + xi.y*p.y + xz*z;
        float sqj = p.x*p.x + p.y*p.y + z*z;
        float d2  = (sqi - 2.0f*dot) + sqj;      // matches (sq_i - 2*xy) + sq_j
        unsigned long long key = ((unsigned long long)fenc(d2) << 32) | (unsigned)j;
        if (j == i) key = U64MAX;
        if (key < kk[KNN-1]) {
            kk[KNN-1] = key;
            #pragma unroll
            for (int q = KNN-1; q > 0; --q) {    // single bubble pass keeps sorted
                unsigned long long a = kk[q-1], b = kk[q];
                kk[q-1] = a < b ? a : b;
                kk[q]   = a < b ? b : a;
            }
        }
    }
    __syncthreads();                              // points no longer needed

    unsigned long long* my = (unsigned long long*)sbuf + w*512;  // 480 used
    #pragma unroll
    for (int q = 0; q < KNN; ++q) my[lane*KNN + q] = kk[q];
    __syncwarp();

    for (int p = 0; p < KNN; ++p) {
        unsigned long long m = U64MAX; int mi = -1;
        #pragma unroll
        for (int c = 0; c < KNN; ++c) {
            int idx = lane + 32*c;                // covers 0..479
            unsigned long long v = my[idx];
            if (v < m) { m = v; mi = idx; }
        }
        unsigned long long gm = m;
        #pragma unroll
        for (int o = 16; o; o >>= 1) {
            unsigned long long s = __shfl_xor_sync(0xffffffffu, gm, o);
            gm = umin64(gm, s);
        }
        if (m == gm && mi >= 0) my[mi] = U64MAX;  // keys unique -> one lane fires
        if (lane == 0) g_knn[i*KNN + p] = (int)(gm & 0xFFFFFFFFu);
        __syncwarp();
    }
}

// count original edges per row/col (for CSR/CSC of S)
__global__ void k_count(const long long* __restrict__ e64,
                        const int* __restrict__ e32, int E) {
    int is64 = g_is64;
    int e = blockIdx.x * blockDim.x + threadIdx.x;
    if (e >= E) return;
    int r, c; edge_rc(e64, e32, E, is64, e, r, c);
    atomicAdd(&g_rowcnt[r], 1);
    atomicAdd(&g_colcnt[c], 1);
}

// exclusive scan: block 0 rows (+xfill = rowptr + 15*i), block 1 cols
__global__ void k_scan() {
    int isrow = (blockIdx.x == 0);
    const int* cnt = isrow ? g_rowcnt : g_colcnt;
    int* ptr  = isrow ? g_rowptr  : g_colptr;
    int* fill = isrow ? g_rowfill : g_colfill;
    __shared__ int sh[1024];
    int t = threadIdx.x;
    int v[4]; int s = 0;
    #pragma unroll
    for (int k = 0; k < 4; ++k) { v[k] = cnt[t*4 + k]; s += v[k]; }
    sh[t] = s;
    __syncthreads();
    for (int d = 1; d < 1024; d <<= 1) {
        int add = (t >= d) ? sh[t - d] : 0;
        __syncthreads();
        sh[t] += add;
        __syncthreads();
    }
    int excl = sh[t] - s;
    #pragma unroll
    for (int k = 0; k < 4; ++k) {
        int idx = t*4 + k;
        ptr[idx] = excl; fill[idx] = excl;
        if (isrow) g_xfill[idx] = excl + KNN*idx;
        excl += v[k];
    }
    if (t == 1023) ptr[Nn] = excl;
}

// scatter extended adjacency (orig edges + kNN) into xcols
__global__ void k_xscatter(const long long* __restrict__ e64,
                           const int* __restrict__ e32, int E) {
    int is64 = g_is64;
    int t = blockIdx.x * blockDim.x + threadIdx.x;
    if (t < E) {
        int r, c; edge_rc(e64, e32, E, is64, t, r, c);
        int p = atomicAdd(&g_xfill[r], 1);
        g_xcols[p] = c;
    } else if (t < E + NK) {
        int ke = t - E;
        int r = ke / KNN;
        int p = atomicAdd(&g_xfill[r], 1);
        g_xcols[p] = g_knn[ke] & NMASK;
    }
}

// per-node per-feature min of y over extended neighbors (gather, no atomics)
__global__ void k_min() {
    __shared__ float red[256];
    int i = blockIdx.x, t = threadIdx.x;
    int f = t & 63, c = t >> 6;
    int x0 = g_rowptr[i]   + KNN * i;
    int x1 = g_rowptr[i+1] + KNN * (i+1);
    float m = FLT_MAX;
    for (int p = x0 + c; p < x1; p += 4) {
        int col = g_xcols[p];
        m = fminf(m, g_y[col*Hh + f]);
    }
    red[t] = m;
    __syncthreads();
    if (t < 128) red[t] = fminf(red[t], red[t + 128]);
    __syncthreads();
    if (t < 64) g_minv[i*Hh + t] = fminf(red[t], red[t + 64]);
}

// feats = (y + b_theta - min) @ W_phi^T + b_phi      (32 rows/block)
__global__ void k_feats(const float* __restrict__ bth,
                        const float* __restrict__ Wphi,
                        const float* __restrict__ bphi) {
    __shared__ float sWt[Hh*Hh];
    __shared__ float sA[32*Hh];
    int t = threadIdx.x;
    int r0 = blockIdx.x * 32;
    for (int idx = t; idx < Hh*Hh; idx += 256) {
        int f = idx >> 6, h = idx & 63;
        sWt[h*Hh + f] = Wphi[idx];
    }
    for (int idx = t; idx < 32*Hh; idx += 256) {
        int f = idx & 63;
        int gi = r0*Hh + idx;
        sA[idx] = g_y[gi] + bth[f] - g_minv[gi];
    }
    __syncthreads();
    for (int o = t; o < 32*Hh; o += 256) {
        int li = o >> 6, f = o & 63;
        float acc = bphi[f];
        #pragma unroll
        for (int h = 0; h < Hh; ++h) acc += sA[li*Hh + h] * sWt[h*Hh + f];
        g_feats[r0*Hh + o] = acc;
    }
}

// q = feats @ W_q^T,  k = feats @ W_k^T
__global__ void k_qk(const float* __restrict__ Wq, const float* __restrict__ Wk) {
    __shared__ float sWq[Hh*Hh];
    __shared__ float sWk[Hh*Hh];
    __shared__ float sF[32*Hh];
    int t = threadIdx.x;
    int r0 = blockIdx.x * 32;
    for (int idx = t; idx < Hh*Hh; idx += 256) {
        int f = idx >> 6, h = idx & 63;
        sWq[h*Hh + f] = Wq[idx];
        sWk[h*Hh + f] = Wk[idx];
    }
    for (int idx = t; idx < 32*Hh; idx += 256) sF[idx] = g_feats[r0*Hh + idx];
    __syncthreads();
    for (int o = t; o < 32*Hh; o += 256) {
        int li = o >> 6, f = o & 63;
        float aq = 0.0f, ak = 0.0f;
        #pragma unroll
        for (int h = 0; h < Hh; ++h) {
            float fv = sF[li*Hh + h];
            aq += fv * sWq[h*Hh + f];
            ak += fv * sWk[h*Hh + f];
        }
        g_q[r0*Hh + o] = aq;
        g_k[r0*Hh + o] = ak;
    }
}

// attn[e] = dot(q[row], k[col]); row-max via encoded atomicMax. warp/edge.
__global__ void k_attn(const long long* __restrict__ e64,
                       const int* __restrict__ e32, int E) {
    int is64 = g_is64;
    int w = (blockIdx.x * blockDim.x + threadIdx.x) >> 5;
    int lane = threadIdx.x & 31;
    if (w >= E) return;
    int row, col;
    edge_rc(e64, e32, E, is64, w, row, col);
    float a = g_q[row*Hh + lane]      * g_k[col*Hh + lane]
            + g_q[row*Hh + 32 + lane] * g_k[col*Hh + 32 + lane];
    #pragma unroll
    for (int o = 16; o; o >>= 1) a += __shfl_xor_sync(0xffffffffu, a, o);
    if (lane == 0) {
        g_attn[w] = a;
        atomicMax(&g_rowmaxkey[row], fenc(a));
    }
}

__global__ void k_exp(const long long* __restrict__ e64,
                      const int* __restrict__ e32, int E) {
    int is64 = g_is64;
    int e = blockIdx.x * blockDim.x + threadIdx.x;
    if (e >= E) return;
    int row, col;
    edge_rc(e64, e32, E, is64, e, row, col);
    float v = expf(g_attn[e] - fdec(g_rowmaxkey[row]));
    g_attn[e] = v;
    atomicAdd(&g_rowsum[row], v);
}

// normalize + scatter S into packed CSR and CSC (duplicates kept)
__global__ void k_sscatter(const long long* __restrict__ e64,
                           const int* __restrict__ e32, int E) {
    int is64 = g_is64;
    int e = blockIdx.x * blockDim.x + threadIdx.x;
    if (e >= E) return;
    int row, col;
    edge_rc(e64, e32, E, is64, e, row, col);
    float sc = g_attn[e] / g_rowsum[row];
    unsigned long long pv = ((unsigned long long)__float_as_uint(sc)) << 32;
    int p = atomicAdd(&g_rowfill[row], 1);
    g_rowpack[p] = pv | (unsigned)col;
    int c = atomicAdd(&g_colfill[col], 1);
    g_cscpack[c] = pv | (unsigned)row;
}

// A_s row i: warp per S-entry p, lane per A-entry qq, serial over CSC col
__global__ void k_out(float* __restrict__ out) {
    __shared__ float orow[Nn];   // 16 KB
    int i = blockIdx.x, t = threadIdx.x;
    int lane = t & 31, w = t >> 5;
    for (int j = t; j < Nn; j += 256) orow[j] = 0.0f;
    __syncthreads();
    int r0 = g_rowptr[i], r1 = g_rowptr[i+1];
    for (int p = r0 + w; p < r1; p += 8) {
        unsigned long long pk = g_rowpack[p];
        int k = (int)(pk & 0xFFFFFFFFu);
        float s = __uint_as_float((unsigned)(pk >> 32));
        int a0 = g_rowptr[k], a1 = g_rowptr[k+1];
        for (int qq = a0 + lane; qq < a1; qq += 32) {
            int l = (int)(g_rowpack[qq] & 0xFFFFFFFFu);
            int c0 = g_colptr[l], c1 = g_colptr[l+1];
            for (int r = c0; r < c1; ++r) {
                unsigned long long ck = g_cscpack[r];
                atomicAdd(&orow[(unsigned)(ck & 0xFFFFFFFFu)],
                          s * __uint_as_float((unsigned)(ck >> 32)));
            }
        }
    }
    __syncthreads();
    float4* o4 = (float4*)(out + (size_t)i * Nn);
    for (int j = t; j < Nn/4; j += 256)
        o4[j] = make_float4(orow[4*j], orow[4*j+1], orow[4*j+2], orow[4*j+3]);
}

// ---------------- launch ----------------
extern "C" void kernel_launch(void* const* d_in, const int* in_sizes, int n_in,
                              void* d_out, int out_size) {
    const float* x    = (const float*)d_in[0];
    const void*  ei   = d_in[1];
    const float* Wth  = (const float*)d_in[2];
    const float* bth  = (const float*)d_in[3];
    const float* Wphi = (const float*)d_in[4];
    const float* bphi = (const float*)d_in[5];
    const float* Wq   = (const float*)d_in[6];
    const float* Wk   = (const float*)d_in[7];
    float* out = (float*)d_out;

    int E = in_sizes[1] / 2;
    const long long* e64 = (const long long*)ei;
    const int*       e32 = (const int*)ei;

    k_detect<<<1, 32>>>((const unsigned long long*)ei);
    k_init<<<(Nn + 255)/256, 256>>>();
    k_y<<<(Nn*Hh + 255)/256, 256>>>(x, Wth);
    k_knn<<<Nn/8, 256>>>(x);
    k_count<<<(E + 255)/256, 256>>>(e64, e32, E);
    k_scan<<<2, 1024>>>();
    k_xscatter<<<(E + NK + 255)/256, 256>>>(e64, e32, E);
    k_min<<<Nn, 256>>>();
    k_feats<<<Nn/32, 256>>>(bth, Wphi, bphi);
    k_qk<<<Nn/32, 256>>>(Wq, Wk);
    k_attn<<<(E*32 + 255)/256, 256>>>(e64, e32, E);
    k_exp<<<(E + 255)/256, 256>>>(e64, e32, E);
    k_sscatter<<<(E + 255)/256, 256>>>(e64, e32, E);
    k_out<<<Nn, 256>>>(out);
}

// round 4
// speedup vs baseline: 2.9278x; 1.5199x over previous
#include <cuda_runtime.h>
#include <cstdint>
#include <float.h>

#define Nn    4096
#define NMASK 4095
#define Hh    64
#define KNN   15
#define MAXE  65536
#define NK    (Nn*KNN)
#define XMAX  (MAXE+NK)
#define CAND  320
#define U64MAX 0xFFFFFFFFFFFFFFFFULL

// ---------------- scratch (device globals; no allocs) ----------------
__device__ int      g_is64;
__device__ float    g_y[Nn*Hh];
__device__ float    g_minv[Nn*Hh];
__device__ float    g_feats[Nn*Hh];
__device__ float    g_q[Nn*Hh];
__device__ float    g_k[Nn*Hh];
__device__ int      g_knn[NK];
__device__ float    g_attn[MAXE];
__device__ unsigned g_rowmaxkey[Nn];
__device__ float    g_rowsum[Nn];
__device__ int      g_rowcnt[Nn];
__device__ int      g_colcnt[Nn];
__device__ int      g_rowptr[Nn+1];
__device__ int      g_colptr[Nn+1];
__device__ int      g_rowfill[Nn];
__device__ int      g_colfill[Nn];
__device__ int      g_xfill[Nn];
__device__ int      g_xcols[XMAX];
__device__ unsigned long long g_rowpack[MAXE];  // (f32bits(val)<<32)|col  CSR of S
__device__ unsigned long long g_cscpack[MAXE];  // (f32bits(val)<<32)|row  CSC of S

// ---------------- helpers ----------------
__device__ __forceinline__ unsigned fenc(float f) {
    unsigned u = __float_as_uint(f);
    return (u & 0x80000000u) ? ~u : (u ^ 0x80000000u);
}
__device__ __forceinline__ float fdec(unsigned e) {
    unsigned u = (e & 0x80000000u) ? (e ^ 0x80000000u) : ~e;
    return __uint_as_float(u);
}
__device__ __forceinline__ void edge_rc(const long long* e64, const int* e32,
                                        int E, int is64, int e, int& r, int& c) {
    if (is64) { r = ((int)e64[e]) & NMASK; c = ((int)e64[E + e]) & NMASK; }
    else      { r = e32[e] & NMASK;        c = e32[E + e] & NMASK; }
}
__device__ __forceinline__ unsigned long long umin64(unsigned long long a,
                                                     unsigned long long b) {
    return a < b ? a : b;
}

// ---------------- kernels ----------------
__global__ void k_detect(const unsigned long long* ei) {
    if (threadIdx.x == 0 && blockIdx.x == 0) {
        int ok64 = 1;
        for (int i = 0; i < 64; ++i) {
            unsigned long long v = ei[i];
            if ((v >> 32) != 0ULL || (v & 0xFFFFFFFFULL) >= (unsigned)Nn) { ok64 = 0; break; }
        }
        g_is64 = ok64;
    }
}

__global__ void k_init() {
    int t = blockIdx.x * blockDim.x + threadIdx.x;
    if (t < Nn) {
        g_rowmaxkey[t] = 0u;
        g_rowsum[t] = 0.0f;
        g_rowcnt[t] = 0;
        g_colcnt[t] = 0;
    }
}

// y = x @ W_theta^T (bias folded later)
__global__ void k_y(const float* __restrict__ x, const float* __restrict__ Wt) {
    int t = blockIdx.x * blockDim.x + threadIdx.x;
    if (t >= Nn * Hh) return;
    int i = t >> 6, f = t & 63;
    float x0 = x[i*3+0], x1 = x[i*3+1], x2 = x[i*3+2];
    g_y[t] = Wt[f*3+0]*x0 + Wt[f*3+1]*x1 + Wt[f*3+2]*x2;
}

// kNN v3: block per query. Keys live in registers (16/thread).
// T = 15th smallest of the 256 per-thread minima is a PROVEN upper bound on
// the true 15th-NN key (order stats on a sub-multiset); collect keys <= T
// (~15-20 of them) and exact-select with (key,idx) u64 packing (JAX ties).
__global__ void k_knn(const float* __restrict__ x) {
    __shared__ unsigned smin[256];
    __shared__ unsigned long long scand[CAND];
    __shared__ int scnt;
    __shared__ unsigned sT;
    int i = blockIdx.x, t = threadIdx.x;

    float xi0 = x[i*3+0], xi1 = x[i*3+1], xi2 = x[i*3+2];
    float sqi = xi0*xi0 + xi1*xi1 + xi2*xi2;

    unsigned key[16];
    unsigned mloc = 0xFFFFFFFFu;
    #pragma unroll
    for (int u = 0; u < 16; ++u) {
        int j = u*256 + t;
        float y0 = x[j*3+0], y1 = x[j*3+1], y2 = x[j*3+2];
        float dot = xi0*y0 + xi1*y1 + xi2*y2;
        float sqj = y0*y0 + y1*y1 + y2*y2;
        float d2  = (sqi - 2.0f*dot) + sqj;     // matches (sq_i - 2*xy) + sq_j
        unsigned kk = fenc(d2);
        if (j == i) kk = 0xFFFFFFFFu;           // exclude self
        key[u] = kk;
        mloc = mloc < kk ? mloc : kk;
    }
    smin[t] = mloc;
    if (t == 0) scnt = 0;
    __syncthreads();

    // warp 0: T = 15th smallest of 256 minima (pack tid for unique removal)
    if (t < 32) {
        unsigned long long v[8];
        #pragma unroll
        for (int u = 0; u < 8; ++u)
            v[u] = ((unsigned long long)smin[u*32 + t] << 32) | (unsigned)(u*32 + t);
        unsigned long long last = 0;
        for (int r = 0; r < KNN; ++r) {
            unsigned long long m = U64MAX;
            #pragma unroll
            for (int u = 0; u < 8; ++u) m = umin64(m, v[u]);
            #pragma unroll
            for (int o = 16; o; o >>= 1) {
                unsigned long long s = __shfl_xor_sync(0xffffffffu, m, o);
                m = umin64(m, s);
            }
            #pragma unroll
            for (int u = 0; u < 8; ++u) if (v[u] == m) v[u] = U64MAX;
            last = m;
        }
        if (t == 0) sT = (unsigned)(last >> 32);
    }
    __syncthreads();

    unsigned T = sT;
    #pragma unroll
    for (int u = 0; u < 16; ++u) {
        if (key[u] <= T) {
            int p = atomicAdd(&scnt, 1);
            if (p < CAND)
                scand[p] = ((unsigned long long)key[u] << 32) | (unsigned)(u*256 + t);
        }
    }
    __syncthreads();

    int cnt = scnt;                              // >= 15 by construction
    if (cnt == KNN) {
        if (t < KNN) g_knn[i*KNN + t] = (int)(scand[t] & 0xFFFFFFFFu);
    } else if (t < 32) {
        unsigned long long v[10];                // 320 slots
        #pragma unroll
        for (int u = 0; u < 10; ++u) {
            int idx = u*32 + t;
            v[u] = (idx < cnt) ? scand[idx] : U64MAX;
        }
        for (int r = 0; r < KNN; ++r) {
            unsigned long long m = U64MAX;
            #pragma unroll
            for (int u = 0; u < 10; ++u) m = umin64(m, v[u]);
            #pragma unroll
            for (int o = 16; o; o >>= 1) {
                unsigned long long s = __shfl_xor_sync(0xffffffffu, m, o);
                m = umin64(m, s);
            }
            #pragma unroll
            for (int u = 0; u < 10; ++u) if (v[u] == m) v[u] = U64MAX;
            if (t == 0) g_knn[i*KNN + r] = (int)(m & 0xFFFFFFFFu);
        }
    }
}

// count original edges per row/col (for CSR/CSC of S)
__global__ void k_count(const long long* __restrict__ e64,
                        const int* __restrict__ e32, int E) {
    int is64 = g_is64;
    int e = blockIdx.x * blockDim.x + threadIdx.x;
    if (e >= E) return;
    int r, c; edge_rc(e64, e32, E, is64, e, r, c);
    atomicAdd(&g_rowcnt[r], 1);
    atomicAdd(&g_colcnt[c], 1);
}

// exclusive scan: block 0 rows (+xfill = rowptr + 15*i), block 1 cols
__global__ void k_scan() {
    int isrow = (blockIdx.x == 0);
    const int* cnt = isrow ? g_rowcnt : g_colcnt;
    int* ptr  = isrow ? g_rowptr  : g_colptr;
    int* fill = isrow ? g_rowfill : g_colfill;
    __shared__ int sh[1024];
    int t = threadIdx.x;
    int v[4]; int s = 0;
    #pragma unroll
    for (int k = 0; k < 4; ++k) { v[k] = cnt[t*4 + k]; s += v[k]; }
    sh[t] = s;
    __syncthreads();
    for (int d = 1; d < 1024; d <<= 1) {
        int add = (t >= d) ? sh[t - d] : 0;
        __syncthreads();
        sh[t] += add;
        __syncthreads();
    }
    int excl = sh[t] - s;
    #pragma unroll
    for (int k = 0; k < 4; ++k) {
        int idx = t*4 + k;
        ptr[idx] = excl; fill[idx] = excl;
        if (isrow) g_xfill[idx] = excl + KNN*idx;
        excl += v[k];
    }
    if (t == 1023) ptr[Nn] = excl;
}

// scatter extended adjacency (orig edges + kNN) into xcols
__global__ void k_xscatter(const long long* __restrict__ e64,
                           const int* __restrict__ e32, int E) {
    int is64 = g_is64;
    int t = blockIdx.x * blockDim.x + threadIdx.x;
    if (t < E) {
        int r, c; edge_rc(e64, e32, E, is64, t, r, c);
        int p = atomicAdd(&g_xfill[r], 1);
        g_xcols[p] = c;
    } else if (t < E + NK) {
        int ke = t - E;
        int r = ke / KNN;
        int p = atomicAdd(&g_xfill[r], 1);
        g_xcols[p] = g_knn[ke] & NMASK;
    }
}

// per-node per-feature min of y over extended neighbors (gather, no atomics)
__global__ void k_min() {
    __shared__ float red[256];
    int i = blockIdx.x, t = threadIdx.x;
    int f = t & 63, c = t >> 6;
    int x0 = g_rowptr[i]   + KNN * i;
    int x1 = g_rowptr[i+1] + KNN * (i+1);
    float m = FLT_MAX;
    for (int p = x0 + c; p < x1; p += 4) {
        int col = g_xcols[p];
        m = fminf(m, g_y[col*Hh + f]);
    }
    red[t] = m;
    __syncthreads();
    if (t < 128) red[t] = fminf(red[t], red[t + 128]);
    __syncthreads();
    if (t < 64) g_minv[i*Hh + t] = fminf(red[t], red[t + 64]);
}

// feats = (y + b_theta - min) @ W_phi^T + b_phi      (32 rows/block)
__global__ void k_feats(const float* __restrict__ bth,
                        const float* __restrict__ Wphi,
                        const float* __restrict__ bphi) {
    __shared__ float sWt[Hh*Hh];
    __shared__ float sA[32*Hh];
    int t = threadIdx.x;
    int r0 = blockIdx.x * 32;
    for (int idx = t; idx < Hh*Hh; idx += 256) {
        int f = idx >> 6, h = idx & 63;
        sWt[h*Hh + f] = Wphi[idx];
    }
    for (int idx = t; idx < 32*Hh; idx += 256) {
        int f = idx & 63;
        int gi = r0*Hh + idx;
        sA[idx] = g_y[gi] + bth[f] - g_minv[gi];
    }
    __syncthreads();
    for (int o = t; o < 32*Hh; o += 256) {
        int li = o >> 6, f = o & 63;
        float acc = bphi[f];
        #pragma unroll
        for (int h = 0; h < Hh; ++h) acc += sA[li*Hh + h] * sWt[h*Hh + f];
        g_feats[r0*Hh + o] = acc;
    }
}

// q = feats @ W_q^T,  k = feats @ W_k^T
__global__ void k_qk(const float* __restrict__ Wq, const float* __restrict__ Wk) {
    __shared__ float sWq[Hh*Hh];
    __shared__ float sWk[Hh*Hh];
    __shared__ float sF[32*Hh];
    int t = threadIdx.x;
    int r0 = blockIdx.x * 32;
    for (int idx = t; idx < Hh*Hh; idx += 256) {
        int f = idx >> 6, h = idx & 63;
        sWq[h*Hh + f] = Wq[idx];
        sWk[h*Hh + f] = Wk[idx];
    }
    for (int idx = t; idx < 32*Hh; idx += 256) sF[idx] = g_feats[r0*Hh + idx];
    __syncthreads();
    for (int o = t; o < 32*Hh; o += 256) {
        int li = o >> 6, f = o & 63;
        float aq = 0.0f, ak = 0.0f;
        #pragma unroll
        for (int h = 0; h < Hh; ++h) {
            float fv = sF[li*Hh + h];
            aq += fv * sWq[h*Hh + f];
            ak += fv * sWk[h*Hh + f];
        }
        g_q[r0*Hh + o] = aq;
        g_k[r0*Hh + o] = ak;
    }
}

// attn[e] = dot(q[row], k[col]); row-max via encoded atomicMax. warp/edge.
__global__ void k_attn(const long long* __restrict__ e64,
                       const int* __restrict__ e32, int E) {
    int is64 = g_is64;
    int w = (blockIdx.x * blockDim.x + threadIdx.x) >> 5;
    int lane = threadIdx.x & 31;
    if (w >= E) return;
    int row, col;
    edge_rc(e64, e32, E, is64, w, row, col);
    float a = g_q[row*Hh + lane]      * g_k[col*Hh + lane]
            + g_q[row*Hh + 32 + lane] * g_k[col*Hh + 32 + lane];
    #pragma unroll
    for (int o = 16; o; o >>= 1) a += __shfl_xor_sync(0xffffffffu, a, o);
    if (lane == 0) {
        g_attn[w] = a;
        atomicMax(&g_rowmaxkey[row], fenc(a));
    }
}

__global__ void k_exp(const long long* __restrict__ e64,
                      const int* __restrict__ e32, int E) {
    int is64 = g_is64;
    int e = blockIdx.x * blockDim.x + threadIdx.x;
    if (e >= E) return;
    int row, col;
    edge_rc(e64, e32, E, is64, e, row, col);
    float v = expf(g_attn[e] - fdec(g_rowmaxkey[row]));
    g_attn[e] = v;
    atomicAdd(&g_rowsum[row], v);
}

// normalize + scatter S into packed CSR and CSC (duplicates kept)
__global__ void k_sscatter(const long long* __restrict__ e64,
                           const int* __restrict__ e32, int E) {
    int is64 = g_is64;
    int e = blockIdx.x * blockDim.x + threadIdx.x;
    if (e >= E) return;
    int row, col;
    edge_rc(e64, e32, E, is64, e, row, col);
    float sc = g_attn[e] / g_rowsum[row];
    unsigned long long pv = ((unsigned long long)__float_as_uint(sc)) << 32;
    int p = atomicAdd(&g_rowfill[row], 1);
    g_rowpack[p] = pv | (unsigned)col;
    int c = atomicAdd(&g_colfill[col], 1);
    g_cscpack[c] = pv | (unsigned)row;
}

// A_s row i: 512 threads, warp per S-entry p, lane per A-entry qq
__global__ void k_out(float* __restrict__ out) {
    __shared__ float orow[Nn];   // 16 KB
    int i = blockIdx.x, t = threadIdx.x;
    int lane = t & 31, w = t >> 5;               // 16 warps
    for (int j = t; j < Nn; j += 512) orow[j] = 0.0f;
    __syncthreads();
    int r0 = g_rowptr[i], r1 = g_rowptr[i+1];
    for (int p = r0 + w; p < r1; p += 16) {
        unsigned long long pk = g_rowpack[p];
        int k = (int)(pk & 0xFFFFFFFFu);
        float s = __uint_as_float((unsigned)(pk >> 32));
        int a0 = g_rowptr[k], a1 = g_rowptr[k+1];
        for (int qq = a0 + lane; qq < a1; qq += 32) {
            int l = (int)(g_rowpack[qq] & 0xFFFFFFFFu);
            int c0 = g_colptr[l], c1 = g_colptr[l+1];
            for (int r = c0; r < c1; ++r) {
                unsigned long long ck = g_cscpack[r];
                atomicAdd(&orow[(unsigned)(ck & 0xFFFFFFFFu)],
                          s * __uint_as_float((unsigned)(ck >> 32)));
            }
        }
    }
    __syncthreads();
    float4* o4 = (float4*)(out + (size_t)i * Nn);
    for (int j = t; j < Nn/4; j += 512)
        o4[j] = make_float4(orow[4*j], orow[4*j+1], orow[4*j+2], orow[4*j+3]);
}

// ---------------- launch ----------------
extern "C" void kernel_launch(void* const* d_in, const int* in_sizes, int n_in,
                              void* d_out, int out_size) {
    const float* x    = (const float*)d_in[0];
    const void*  ei   = d_in[1];
    const float* Wth  = (const float*)d_in[2];
    const float* bth  = (const float*)d_in[3];
    const float* Wphi = (const float*)d_in[4];
    const float* bphi = (const float*)d_in[5];
    const float* Wq   = (const float*)d_in[6];
    const float* Wk   = (const float*)d_in[7];
    float* out = (float*)d_out;

    int E = in_sizes[1] / 2;
    const long long* e64 = (const long long*)ei;
    const int*       e32 = (const int*)ei;

    k_detect<<<1, 32>>>((const unsigned long long*)ei);
    k_init<<<(Nn + 255)/256, 256>>>();
    k_y<<<(Nn*Hh + 255)/256, 256>>>(x, Wth);
    k_knn<<<Nn, 256>>>(x);
    k_count<<<(E + 255)/256, 256>>>(e64, e32, E);
    k_scan<<<2, 1024>>>();
    k_xscatter<<<(E + NK + 255)/256, 256>>>(e64, e32, E);
    k_min<<<Nn, 256>>>();
    k_feats<<<Nn/32, 256>>>(bth, Wphi, bphi);
    k_qk<<<Nn/32, 256>>>(Wq, Wk);
    k_attn<<<(E*32 + 255)/256, 256>>>(e64, e32, E);
    k_exp<<<(E + 255)/256, 256>>>(e64, e32, E);
    k_sscatter<<<(E + 255)/256, 256>>>(e64, e32, E);
    k_out<<<Nn, 512>>>(out);
}